// round 2
// baseline (speedup 1.0000x reference)
#include <cuda_runtime.h>
#include <stdint.h>

// ---------------------------------------------------------------------------
// Persistent fp32 RNN:  out[t] = tanh(x[t] @ Wi^T + h @ Wh^T),  h = out[t]
//
// Grid: 8 batch-groups (16 batches each) x 16 H-slice CTAs (32 outputs each)
//       = 128 CTAs, 1 CTA/SM (smem-bound) -> all co-resident.
// Per CTA, SMEM-resident:
//   Ws [768][32]  : rows 0..511 = Wh[j][k] transposed slice, rows 512..767 = Wi
//   Hd [768][36]  : duplicated pairs {v,v} of [h_t | x_t] per batch (16 batches)
//   Ps [8][16][34]: per-warp k-chunk partial sums
// Inner loop: per k, 3x LDS.128 + 8x fma.rn.f32x2 (8 j x 2 b per thread).
// Group sync: global atomic counter, monotonic across graph replays.
// ---------------------------------------------------------------------------

namespace {
constexpr int kT = 1024, kB = 128, kI = 256, kH = 512;
constexpr int KTOT = kH + kI;               // 768
constexpr int NG   = 8;                     // batch groups
constexpr int BG   = kB / NG;               // 16 batches / group
constexpr int NC   = 16;                    // CTAs per group (H slices)
constexpr int JC   = kH / NC;               // 32 outputs / CTA
constexpr int NTHR = 256;
constexpr int NWARP = NTHR / 32;            // 8 (one k-chunk per warp)
constexpr int KCH  = KTOT / NWARP;          // 96 k per chunk

constexpr int WS_STRIDE = JC;               // 32 floats / k-row
constexpr int HD_STRIDE = 36;               // 32 + 4 pad (16B-aligned rows)
constexpr int PS_STRIDE = 34;               // 32 + 2 pad

constexpr int OFF_WS = 0;
constexpr int OFF_HD = OFF_WS + KTOT * WS_STRIDE;             // 24576
constexpr int OFF_PS = OFF_HD + KTOT * HD_STRIDE;             // 52224
constexpr int SMEM_FLOATS = OFF_PS + NWARP * BG * PS_STRIDE;  // 56576
constexpr size_t SMEM_BYTES = size_t(SMEM_FLOATS) * 4;        // 226304 B
}

__device__ unsigned g_rnn_bar[NG];   // zero-init at load; monotonic forever

__device__ __forceinline__ void fma_f32x2(unsigned long long& acc,
                                          unsigned long long a,
                                          unsigned long long b) {
    asm("fma.rn.f32x2 %0, %1, %2, %0;" : "+l"(acc) : "l"(a), "l"(b));
}

__device__ __forceinline__ unsigned long long dup_f32(float v) {
    unsigned u = __float_as_uint(v);
    return (((unsigned long long)u) << 32) | (unsigned long long)u;
}

__global__ void __launch_bounds__(NTHR, 1)
rnn_persistent_kernel(const float* __restrict__ x,
                      const float* __restrict__ Wi,
                      const float* __restrict__ Wh,
                      float* __restrict__ out,
                      int write_tail)
{
    extern __shared__ float sm[];
    float* Ws   = sm + OFF_WS;
    float* Hdup = sm + OFF_HD;
    float* Ps   = sm + OFF_PS;

    const int tid = threadIdx.x;
    const int g   = blockIdx.x >> 4;    // batch group 0..7
    const int c   = blockIdx.x & 15;    // H slice    0..15
    const int bg0 = g * BG;
    const int jg0 = c * JC;

    // ---- prologue: stage weights (one-time) ------------------------------
    // Wh slice -> Ws rows [0,512), k-major, conflict-free STS
    for (int e = tid; e < JC * kH; e += NTHR) {
        int jl = e & (JC - 1);
        int k  = e >> 5;
        Ws[k * WS_STRIDE + jl] = Wh[(size_t)(jg0 + jl) * kH + k];
    }
    // Wi slice -> Ws rows [512,768)
    for (int e = tid; e < JC * kI; e += NTHR) {
        int jl = e & (JC - 1);
        int i  = e >> 5;
        Ws[(kH + i) * WS_STRIDE + jl] = Wi[(size_t)(jg0 + jl) * kI + i];
    }
    // h0 = 0 : zero Hd rows [0,512)
    for (int e = tid; e < kH * HD_STRIDE; e += NTHR) Hdup[e] = 0.f;
    // x[0] -> Hd rows [512,768), duplicated pairs
    {
        const int b16 = tid >> 4, l16 = tid & 15;
        const float* xp = x + (size_t)(bg0 + b16) * kI;
        #pragma unroll
        for (int i = 0; i < kI / 16; ++i) {
            int kk = l16 + 16 * i;
            float v = __ldg(xp + kk);
            *reinterpret_cast<unsigned long long*>(
                &Hdup[(kH + kk) * HD_STRIDE + 2 * b16]) = dup_f32(v);
        }
    }
    __syncthreads();

    // ---- per-thread tile -------------------------------------------------
    const int warp  = tid >> 5;          // k-chunk
    const int lane  = tid & 31;
    const int jq    = lane & 3;          // j octet: j in [jq*8, jq*8+8)
    const int bp    = lane >> 2;         // batch pair: b0 = 2*bp
    const int kbase = warp * KCH;
    const float* wbase = Ws   + (size_t)kbase * WS_STRIDE + jq * 8;
    const float* hbase = Hdup + (size_t)kbase * HD_STRIDE + bp * 4;

    for (int t = 0; t < kT; ++t) {
        unsigned long long a0=0,a1=0,a2=0,a3=0,a4=0,a5=0,a6=0,a7=0;

        // ---- inner: (h|x) . (Wh|Wi) over this warp's 96-k chunk ----------
        const float* wp = wbase;
        const float* hp = hbase;
        #pragma unroll 8
        for (int kk = 0; kk < KCH; ++kk) {
            const ulonglong2 w0 = *reinterpret_cast<const ulonglong2*>(wp);
            const ulonglong2 w1 = *reinterpret_cast<const ulonglong2*>(wp + 4);
            const ulonglong2 hh = *reinterpret_cast<const ulonglong2*>(hp);
            fma_f32x2(a0, w0.x, hh.x);  fma_f32x2(a1, w0.y, hh.x);
            fma_f32x2(a2, w1.x, hh.x);  fma_f32x2(a3, w1.y, hh.x);
            fma_f32x2(a4, w0.x, hh.y);  fma_f32x2(a5, w0.y, hh.y);
            fma_f32x2(a6, w1.x, hh.y);  fma_f32x2(a7, w1.y, hh.y);
            wp += WS_STRIDE;
            hp += HD_STRIDE;
        }
        __syncthreads();

        // ---- scatter partials to Ps --------------------------------------
        {
            unsigned long long acc[8] = {a0,a1,a2,a3,a4,a5,a6,a7};
            #pragma unroll
            for (int bi = 0; bi < 2; ++bi)
                #pragma unroll
                for (int jp = 0; jp < 4; ++jp) {
                    int b   = bp * 2 + bi;
                    int col = jq * 8 + jp * 2;
                    *reinterpret_cast<unsigned long long*>(
                        &Ps[(warp * BG + b) * PS_STRIDE + col]) = acc[jp + 4 * bi];
                }
        }
        // ---- prefetch x[t+1] into Hd rows [512,768) (no dependence) ------
        if (t + 1 < kT) {
            const int b16 = tid >> 4, l16 = tid & 15;
            const float* xp = x + (size_t)(t + 1) * kB * kI
                                + (size_t)(bg0 + b16) * kI;
            #pragma unroll
            for (int i = 0; i < kI / 16; ++i) {
                int kk = l16 + 16 * i;
                float v = __ldg(xp + kk);
                *reinterpret_cast<unsigned long long*>(
                    &Hdup[(kH + kk) * HD_STRIDE + 2 * b16]) = dup_f32(v);
            }
        }
        __syncthreads();

        // ---- reduce 8 partials, tanh, store output -----------------------
        {
            const int b  = tid >> 4;
            const int j0 = (tid & 15) * 2;
            float sx = 0.f, sy = 0.f;
            #pragma unroll
            for (int ks = 0; ks < NWARP; ++ks) {
                float2 p = *reinterpret_cast<const float2*>(
                    &Ps[(ks * BG + b) * PS_STRIDE + j0]);
                sx += p.x; sy += p.y;
            }
            float2 r;
            r.x = tanhf(sx);
            r.y = tanhf(sy);
            size_t o = (size_t)t * kB * kH + (size_t)(bg0 + b) * kH + jg0 + j0;
            *reinterpret_cast<float2*>(out + o) = r;
            if (t == kT - 1 && write_tail) {
                size_t ot = (size_t)kT * kB * kH
                          + (size_t)(bg0 + b) * kH + jg0 + j0;
                *reinterpret_cast<float2*>(out + ot) = r;
            }
        }
        if (t + 1 == kT) break;

        // ---- group barrier (16 CTAs), monotonic counter ------------------
        __threadfence();
        __syncthreads();
        if (tid == 0) {
            unsigned old = atomicAdd(&g_rnn_bar[g], 1u);
            unsigned target = ((old >> 4) + 1u) << 4;
            unsigned cur;
            do {
                asm volatile("ld.acquire.gpu.global.u32 %0, [%1];"
                             : "=r"(cur) : "l"(&g_rnn_bar[g]) : "memory");
            } while (cur < target);
        }
        __syncthreads();

        // ---- read back full h (all 16 batches) from out[t] ---------------
        {
            const int b16 = tid >> 4, l16 = tid & 15;
            const float* op = out + (size_t)t * kB * kH
                                  + (size_t)(bg0 + b16) * kH;
            #pragma unroll 8
            for (int i = 0; i < kH / 16; ++i) {
                int kk = l16 + 16 * i;
                float v = __ldcg(op + kk);
                *reinterpret_cast<unsigned long long*>(
                    &Hdup[kk * HD_STRIDE + 2 * b16]) = dup_f32(v);
            }
        }
        __syncthreads();
    }
}

extern "C" void kernel_launch(void* const* d_in, const int* in_sizes, int n_in,
                              void* d_out, int out_size) {
    const float* x  = (const float*)d_in[0];   // [T,B,I]
    const float* Wi = (const float*)d_in[1];   // [H,I]
    const float* Wh = (const float*)d_in[2];   // [H,H]
    float* out = (float*)d_out;

    const long long main_elems = (long long)kT * kB * kH;
    int write_tail = ((long long)out_size >= main_elems + (long long)kB * kH) ? 1 : 0;

    cudaFuncSetAttribute(rnn_persistent_kernel,
                         cudaFuncAttributeMaxDynamicSharedMemorySize,
                         (int)SMEM_BYTES);
    rnn_persistent_kernel<<<NG * NC, NTHR, SMEM_BYTES>>>(x, Wi, Wh, out, write_tail);
}

// round 3
// speedup vs baseline: 1.0030x; 1.0030x over previous
#include <cuda_runtime.h>
#include <stdint.h>

// ---------------------------------------------------------------------------
// Persistent fp32 RNN:  out[t] = tanh(x[t] @ Wi^T + h @ Wh^T),  h = out[t]
//
// Grid: 8 batch-groups (16 batches each) x 16 H-slice CTAs (32 outputs each)
//       = 128 CTAs, 1 CTA/SM (smem-bound) -> all co-resident.
// Per CTA, SMEM-resident:
//   Ws [768][32]  : rows 0..511 = Wh[j][k] transposed slice, rows 512..767 = Wi
//   Hd [768][36]  : duplicated pairs {v,v} of [h_t | x_t] per batch (16 batches)
//   Ps [8][16][34]: per-warp k-chunk partial sums
// Inner loop: per k, 3x LDS.128 + 8x fma.rn.f32x2 (8 j x 2 b per thread).
// Group sync: global atomic counter, monotonic across graph replays.
// ---------------------------------------------------------------------------

namespace {
constexpr int kT = 1024, kB = 128, kI = 256, kH = 512;
constexpr int KTOT = kH + kI;               // 768
constexpr int NG   = 8;                     // batch groups
constexpr int BG   = kB / NG;               // 16 batches / group
constexpr int NC   = 16;                    // CTAs per group (H slices)
constexpr int JC   = kH / NC;               // 32 outputs / CTA
constexpr int NTHR = 256;
constexpr int NWARP = NTHR / 32;            // 8 (one k-chunk per warp)
constexpr int KCH  = KTOT / NWARP;          // 96 k per chunk

constexpr int WS_STRIDE = JC;               // 32 floats / k-row
constexpr int HD_STRIDE = 36;               // 32 + 4 pad (16B-aligned rows)
constexpr int PS_STRIDE = 34;               // 32 + 2 pad

constexpr int OFF_WS = 0;
constexpr int OFF_HD = OFF_WS + KTOT * WS_STRIDE;             // 24576
constexpr int OFF_PS = OFF_HD + KTOT * HD_STRIDE;             // 52224
constexpr int SMEM_FLOATS = OFF_PS + NWARP * BG * PS_STRIDE;  // 56576
constexpr size_t SMEM_BYTES = size_t(SMEM_FLOATS) * 4;        // 226304 B
}

__device__ unsigned g_rnn_bar[NG];   // zero-init at load; monotonic forever

__device__ __forceinline__ void fma_f32x2(unsigned long long& acc,
                                          unsigned long long a,
                                          unsigned long long b) {
    asm("fma.rn.f32x2 %0, %1, %2, %0;" : "+l"(acc) : "l"(a), "l"(b));
}

__device__ __forceinline__ unsigned long long dup_f32(float v) {
    unsigned u = __float_as_uint(v);
    return (((unsigned long long)u) << 32) | (unsigned long long)u;
}

__global__ void __launch_bounds__(NTHR, 1)
rnn_persistent_kernel(const float* __restrict__ x,
                      const float* __restrict__ Wi,
                      const float* __restrict__ Wh,
                      float* __restrict__ out,
                      int write_tail)
{
    extern __shared__ float sm[];
    float* Ws   = sm + OFF_WS;
    float* Hdup = sm + OFF_HD;
    float* Ps   = sm + OFF_PS;

    const int tid = threadIdx.x;
    const int g   = blockIdx.x >> 4;    // batch group 0..7
    const int c   = blockIdx.x & 15;    // H slice    0..15
    const int bg0 = g * BG;
    const int jg0 = c * JC;

    // ---- prologue: stage weights (one-time) ------------------------------
    // Wh slice -> Ws rows [0,512), k-major, conflict-free STS
    for (int e = tid; e < JC * kH; e += NTHR) {
        int jl = e & (JC - 1);
        int k  = e >> 5;
        Ws[k * WS_STRIDE + jl] = Wh[(size_t)(jg0 + jl) * kH + k];
    }
    // Wi slice -> Ws rows [512,768)
    for (int e = tid; e < JC * kI; e += NTHR) {
        int jl = e & (JC - 1);
        int i  = e >> 5;
        Ws[(kH + i) * WS_STRIDE + jl] = Wi[(size_t)(jg0 + jl) * kI + i];
    }
    // h0 = 0 : zero Hd rows [0,512)
    for (int e = tid; e < kH * HD_STRIDE; e += NTHR) Hdup[e] = 0.f;
    // x[0] -> Hd rows [512,768), duplicated pairs
    {
        const int b16 = tid >> 4, l16 = tid & 15;
        const float* xp = x + (size_t)(bg0 + b16) * kI;
        #pragma unroll
        for (int i = 0; i < kI / 16; ++i) {
            int kk = l16 + 16 * i;
            float v = __ldg(xp + kk);
            *reinterpret_cast<unsigned long long*>(
                &Hdup[(kH + kk) * HD_STRIDE + 2 * b16]) = dup_f32(v);
        }
    }
    __syncthreads();

    // ---- per-thread tile -------------------------------------------------
    const int warp  = tid >> 5;          // k-chunk
    const int lane  = tid & 31;
    const int jq    = lane & 3;          // j octet: j in [jq*8, jq*8+8)
    const int bp    = lane >> 2;         // batch pair: b0 = 2*bp
    const int kbase = warp * KCH;
    const float* wbase = Ws   + (size_t)kbase * WS_STRIDE + jq * 8;
    const float* hbase = Hdup + (size_t)kbase * HD_STRIDE + bp * 4;

    for (int t = 0; t < kT; ++t) {
        unsigned long long a0=0,a1=0,a2=0,a3=0,a4=0,a5=0,a6=0,a7=0;

        // ---- inner: (h|x) . (Wh|Wi) over this warp's 96-k chunk ----------
        const float* wp = wbase;
        const float* hp = hbase;
        #pragma unroll 8
        for (int kk = 0; kk < KCH; ++kk) {
            const ulonglong2 w0 = *reinterpret_cast<const ulonglong2*>(wp);
            const ulonglong2 w1 = *reinterpret_cast<const ulonglong2*>(wp + 4);
            const ulonglong2 hh = *reinterpret_cast<const ulonglong2*>(hp);
            fma_f32x2(a0, w0.x, hh.x);  fma_f32x2(a1, w0.y, hh.x);
            fma_f32x2(a2, w1.x, hh.x);  fma_f32x2(a3, w1.y, hh.x);
            fma_f32x2(a4, w0.x, hh.y);  fma_f32x2(a5, w0.y, hh.y);
            fma_f32x2(a6, w1.x, hh.y);  fma_f32x2(a7, w1.y, hh.y);
            wp += WS_STRIDE;
            hp += HD_STRIDE;
        }
        __syncthreads();

        // ---- scatter partials to Ps --------------------------------------
        {
            unsigned long long acc[8] = {a0,a1,a2,a3,a4,a5,a6,a7};
            #pragma unroll
            for (int bi = 0; bi < 2; ++bi)
                #pragma unroll
                for (int jp = 0; jp < 4; ++jp) {
                    int b   = bp * 2 + bi;
                    int col = jq * 8 + jp * 2;
                    *reinterpret_cast<unsigned long long*>(
                        &Ps[(warp * BG + b) * PS_STRIDE + col]) = acc[jp + 4 * bi];
                }
        }
        // ---- prefetch x[t+1] into Hd rows [512,768) (no dependence) ------
        if (t + 1 < kT) {
            const int b16 = tid >> 4, l16 = tid & 15;
            const float* xp = x + (size_t)(t + 1) * kB * kI
                                + (size_t)(bg0 + b16) * kI;
            #pragma unroll
            for (int i = 0; i < kI / 16; ++i) {
                int kk = l16 + 16 * i;
                float v = __ldg(xp + kk);
                *reinterpret_cast<unsigned long long*>(
                    &Hdup[(kH + kk) * HD_STRIDE + 2 * b16]) = dup_f32(v);
            }
        }
        __syncthreads();

        // ---- reduce 8 partials, tanh, store output -----------------------
        {
            const int b  = tid >> 4;
            const int j0 = (tid & 15) * 2;
            float sx = 0.f, sy = 0.f;
            #pragma unroll
            for (int ks = 0; ks < NWARP; ++ks) {
                float2 p = *reinterpret_cast<const float2*>(
                    &Ps[(ks * BG + b) * PS_STRIDE + j0]);
                sx += p.x; sy += p.y;
            }
            float2 r;
            r.x = tanhf(sx);
            r.y = tanhf(sy);
            size_t o = (size_t)t * kB * kH + (size_t)(bg0 + b) * kH + jg0 + j0;
            *reinterpret_cast<float2*>(out + o) = r;
            if (t == kT - 1 && write_tail) {
                size_t ot = (size_t)kT * kB * kH
                          + (size_t)(bg0 + b) * kH + jg0 + j0;
                *reinterpret_cast<float2*>(out + ot) = r;
            }
        }
        if (t + 1 == kT) break;

        // ---- group barrier (16 CTAs), monotonic counter ------------------
        __threadfence();
        __syncthreads();
        if (tid == 0) {
            unsigned old = atomicAdd(&g_rnn_bar[g], 1u);
            unsigned target = ((old >> 4) + 1u) << 4;
            unsigned cur;
            do {
                asm volatile("ld.acquire.gpu.global.u32 %0, [%1];"
                             : "=r"(cur) : "l"(&g_rnn_bar[g]) : "memory");
            } while (cur < target);
        }
        __syncthreads();

        // ---- read back full h (all 16 batches) from out[t] ---------------
        {
            const int b16 = tid >> 4, l16 = tid & 15;
            const float* op = out + (size_t)t * kB * kH
                                  + (size_t)(bg0 + b16) * kH;
            #pragma unroll 8
            for (int i = 0; i < kH / 16; ++i) {
                int kk = l16 + 16 * i;
                float v = __ldcg(op + kk);
                *reinterpret_cast<unsigned long long*>(
                    &Hdup[kk * HD_STRIDE + 2 * b16]) = dup_f32(v);
            }
        }
        __syncthreads();
    }
}

extern "C" void kernel_launch(void* const* d_in, const int* in_sizes, int n_in,
                              void* d_out, int out_size) {
    const float* x  = (const float*)d_in[0];   // [T,B,I]
    const float* Wi = (const float*)d_in[1];   // [H,I]
    const float* Wh = (const float*)d_in[2];   // [H,H]
    float* out = (float*)d_out;

    const long long main_elems = (long long)kT * kB * kH;
    int write_tail = ((long long)out_size >= main_elems + (long long)kB * kH) ? 1 : 0;

    cudaFuncSetAttribute(rnn_persistent_kernel,
                         cudaFuncAttributeMaxDynamicSharedMemorySize,
                         (int)SMEM_BYTES);
    rnn_persistent_kernel<<<NG * NC, NTHR, SMEM_BYTES>>>(x, Wi, Wh, out, write_tail);
}

// round 4
// speedup vs baseline: 1.4544x; 1.4501x over previous
#include <cuda_runtime.h>
#include <stdint.h>

// ---------------------------------------------------------------------------
// Persistent fp32 RNN with k-pair packed f32x2 math.
//
// out[t] = tanh(x[t] @ Wi^T + h @ Wh^T),  h = out[t]
//
// Grid: 8 batch-groups (16 batches) x 16 H-slice CTAs (32 outputs) = 128 CTAs,
// 512 threads (16 warps). Each warp owns 24 k-pairs of the K=768 reduction
// ([h|x] against [Wh|Wi]). Accumulators hold {even-k, odd-k} partial sums in
// one 64-bit register via fma.rn.f32x2; lo+hi added once per step.
//
// SMEM (u64 units):
//   Ws2 [384 kp][34]  : weight k-pairs, 16B-unit column permute (conflict-free)
//   Hd2 [384 kp][18]  : [h|x] k-pairs per batch (16 batches)
//   Ps  [16 w][16 b][34 fl] : per-warp partials, j-column permuted
// ---------------------------------------------------------------------------

namespace {
constexpr int kT = 1024, kB = 128, kI = 256, kH = 512;
constexpr int NG = 8;                 // batch groups
constexpr int BG = kB / NG;           // 16 batches / group
constexpr int NC = 16;                // CTAs per group (H slices)
constexpr int JC = kH / NC;           // 32 outputs / CTA
constexpr int NTHR = 512;
constexpr int NWARP = NTHR / 32;      // 16
constexpr int KP_H = kH / 2;          // 256 h k-pairs
constexpr int KP_X = kI / 2;          // 128 x k-pairs
constexpr int KPT  = KP_H + KP_X;     // 384
constexpr int KPW  = KPT / NWARP;     // 24 k-pairs per warp

constexpr int WS_STRIDE = 34;         // u64 per Ws2 row (17 x 16B units)
constexpr int HD_STRIDE = 18;         // u64 per Hd2 row (16 b + pad)
constexpr int PS_STRIDE = 34;         // floats per Ps row (32 + pad)

constexpr int OFF_WS = 0;                              // u64 units
constexpr int OFF_HD = KPT * WS_STRIDE;                // 13056
constexpr int OFF_PS = OFF_HD + KPT * HD_STRIDE;       // 19968
constexpr int PS_U64 = NWARP * BG * PS_STRIDE / 2;     // 4352
constexpr int SMEM_U64 = OFF_PS + PS_U64;              // 24320
constexpr size_t SMEM_BYTES = size_t(SMEM_U64) * 8;    // 194560 B
}

__device__ unsigned g_rnn_bar[NG];   // zero-init; monotonic across replays

__device__ __forceinline__ void fma2(unsigned long long& acc,
                                     unsigned long long a,
                                     unsigned long long b) {
    asm("fma.rn.f32x2 %0, %1, %2, %0;" : "+l"(acc) : "l"(a), "l"(b));
}

__global__ void __launch_bounds__(NTHR, 1)
rnn_kpair_kernel(const float* __restrict__ x,
                 const float* __restrict__ Wi,
                 const float* __restrict__ Wh,
                 float* __restrict__ out,
                 int write_tail)
{
    extern __shared__ unsigned long long smu[];
    unsigned long long* Ws = smu + OFF_WS;
    unsigned long long* Hd = smu + OFF_HD;
    float*              Ps = reinterpret_cast<float*>(smu + OFF_PS);
    float2*             Ps2 = reinterpret_cast<float2*>(smu + OFF_PS);

    const int tid = threadIdx.x;
    const int g   = blockIdx.x >> 4;    // batch group 0..7
    const int c   = blockIdx.x & 15;    // H slice    0..15
    const int bg0 = g * BG;
    const int jg0 = c * JC;

    // ---- prologue: stage weight k-pairs (one-time) -----------------------
    // Ws2 u64 index for (kp, j): kp*34 + (j>>2)*2 + ((j>>1)&1)*16 + (j&1)
    {
        const int jl  = tid >> 4;          // 0..31
        const int kpb = tid & 15;          // 0..15
        const int dst = (jl >> 2) * 2 + ((jl >> 1) & 1) * 16 + (jl & 1);
        const float2* whp = reinterpret_cast<const float2*>(
            Wh + (size_t)(jg0 + jl) * kH);
        #pragma unroll
        for (int i = 0; i < KP_H / 16; ++i) {
            int kp = kpb + 16 * i;
            float2 v = __ldg(whp + kp);
            Ws[kp * WS_STRIDE + dst] = *reinterpret_cast<unsigned long long*>(&v);
        }
        const float2* wip = reinterpret_cast<const float2*>(
            Wi + (size_t)(jg0 + jl) * kI);
        #pragma unroll
        for (int i = 0; i < KP_X / 16; ++i) {
            int kp = kpb + 16 * i;
            float2 v = __ldg(wip + kp);
            Ws[(KP_H + kp) * WS_STRIDE + dst] =
                *reinterpret_cast<unsigned long long*>(&v);
        }
    }
    // h0 = 0: zero Hd (all rows, incl. pad)
    for (int e = tid; e < KPT * HD_STRIDE; e += NTHR) Hd[e] = 0ull;
    __syncthreads();
    // x[0] -> Hd rows [KP_H, KPT)
    {
        const int b = tid >> 5, l = tid & 31;
        const float2* xp = reinterpret_cast<const float2*>(
            x + (size_t)(bg0 + b) * kI);
        #pragma unroll
        for (int i = 0; i < 4; ++i) {
            float2 v = __ldcg(xp + l + 32 * i);
            Hd[(KP_H + l + 32 * i) * HD_STRIDE + b] =
                *reinterpret_cast<unsigned long long*>(&v);
        }
    }
    __syncthreads();

    // ---- per-thread tile ---------------------------------------------------
    const int w    = tid >> 5;           // warp = k-chunk 0..15
    const int lane = tid & 31;
    const int jq   = lane & 7;           // j quad: j in [4jq, 4jq+4)
    const int bp   = lane >> 3;          // batch quad: b in [4bp, 4bp+4)
    const int kbase = w * KPW;
    const unsigned long long* wbase = Ws + (size_t)kbase * WS_STRIDE + jq * 2;
    const unsigned long long* hbase = Hd + (size_t)kbase * HD_STRIDE + bp * 4;

    const int rb = tid >> 5;             // reduce/readback batch = warp id
    const int rl = tid & 31;

    for (int t = 0; t < kT; ++t) {
        unsigned long long a00=0,a01=0,a02=0,a03=0,
                           a10=0,a11=0,a12=0,a13=0,
                           a20=0,a21=0,a22=0,a23=0,
                           a30=0,a31=0,a32=0,a33=0;

        // ---- inner: 24 k-pairs, j4 x b4 per thread ------------------------
        const unsigned long long* wp = wbase;
        const unsigned long long* hp = hbase;
        #pragma unroll 8
        for (int i = 0; i < KPW; ++i) {
            const ulonglong2 w0 = *reinterpret_cast<const ulonglong2*>(wp);
            const ulonglong2 w1 = *reinterpret_cast<const ulonglong2*>(wp + 16);
            const ulonglong2 h0 = *reinterpret_cast<const ulonglong2*>(hp);
            const ulonglong2 h1 = *reinterpret_cast<const ulonglong2*>(hp + 2);
            fma2(a00, w0.x, h0.x); fma2(a10, w0.y, h0.x);
            fma2(a20, w1.x, h0.x); fma2(a30, w1.y, h0.x);
            fma2(a01, w0.x, h0.y); fma2(a11, w0.y, h0.y);
            fma2(a21, w1.x, h0.y); fma2(a31, w1.y, h0.y);
            fma2(a02, w0.x, h1.x); fma2(a12, w0.y, h1.x);
            fma2(a22, w1.x, h1.x); fma2(a32, w1.y, h1.x);
            fma2(a03, w0.x, h1.y); fma2(a13, w0.y, h1.y);
            fma2(a23, w1.x, h1.y); fma2(a33, w1.y, h1.y);
            wp += WS_STRIDE;
            hp += HD_STRIDE;
        }

        // ---- combine lo+hi and scatter to Ps (conflict-free permute) ------
        {
            unsigned long long acc[4][4] = {{a00,a01,a02,a03},
                                            {a10,a11,a12,a13},
                                            {a20,a21,a22,a23},
                                            {a30,a31,a32,a33}};
            float s[4][4];
            #pragma unroll
            for (int jj = 0; jj < 4; ++jj)
                #pragma unroll
                for (int bb = 0; bb < 4; ++bb) {
                    float2 f = *reinterpret_cast<float2*>(&acc[jj][bb]);
                    s[jj][bb] = f.x + f.y;
                }
            #pragma unroll
            for (int bb = 0; bb < 4; ++bb) {
                int b = 4 * bp + bb;
                Ps2[(w * BG + b) * 17 + jq]     = make_float2(s[0][bb], s[1][bb]);
                Ps2[(w * BG + b) * 17 + jq + 8] = make_float2(s[2][bb], s[3][bb]);
            }
        }

        // ---- prefetch x[t+1] into regs (independent) ----------------------
        float2 xr0, xr1, xr2, xr3;
        if (t + 1 < kT) {
            const float2* xp = reinterpret_cast<const float2*>(
                x + (size_t)(t + 1) * kB * kI + (size_t)(bg0 + rb) * kI);
            xr0 = __ldcg(xp + rl);
            xr1 = __ldcg(xp + rl + 32);
            xr2 = __ldcg(xp + rl + 64);
            xr3 = __ldcg(xp + rl + 96);
        }
        __syncthreads();

        // ---- reduce 16 partials, tanh, store out[t] -----------------------
        {
            const int b = rb, j = rl;
            const int colf = ((j >> 2) + 8 * ((j >> 1) & 1)) * 2 + (j & 1);
            float sum = 0.f;
            #pragma unroll
            for (int ws = 0; ws < NWARP; ++ws)
                sum += Ps[(ws * BG + b) * PS_STRIDE + colf];
            float r = tanhf(sum);
            size_t o = (size_t)t * kB * kH + (size_t)(bg0 + b) * kH + jg0 + j;
            out[o] = r;
            if (t == kT - 1 && write_tail) {
                out[(size_t)kT * kB * kH + (size_t)(bg0 + b) * kH + jg0 + j] = r;
            }
        }
        // ---- store x[t+1] into Hd x-rows (inner already done) -------------
        if (t + 1 < kT) {
            Hd[(KP_H + rl)      * HD_STRIDE + rb] = *reinterpret_cast<unsigned long long*>(&xr0);
            Hd[(KP_H + rl + 32) * HD_STRIDE + rb] = *reinterpret_cast<unsigned long long*>(&xr1);
            Hd[(KP_H + rl + 64) * HD_STRIDE + rb] = *reinterpret_cast<unsigned long long*>(&xr2);
            Hd[(KP_H + rl + 96) * HD_STRIDE + rb] = *reinterpret_cast<unsigned long long*>(&xr3);
        }
        if (t + 1 == kT) break;

        // ---- group barrier (16 CTAs), monotonic counter -------------------
        __threadfence();
        __syncthreads();
        if (tid == 0) {
            unsigned old = atomicAdd(&g_rnn_bar[g], 1u);
            unsigned target = ((old >> 4) + 1u) << 4;
            unsigned cur;
            do {
                asm volatile("ld.acquire.gpu.global.u32 %0, [%1];"
                             : "=r"(cur) : "l"(&g_rnn_bar[g]) : "memory");
            } while (cur < target);
        }
        __syncthreads();

        // ---- read back full h (16 batches) from out[t] as k-pairs ---------
        {
            const float2* op = reinterpret_cast<const float2*>(
                out + (size_t)t * kB * kH + (size_t)(bg0 + rb) * kH);
            #pragma unroll
            for (int i = 0; i < 8; ++i) {
                float2 v = __ldcg(op + rl + 32 * i);
                Hd[(rl + 32 * i) * HD_STRIDE + rb] =
                    *reinterpret_cast<unsigned long long*>(&v);
            }
        }
        __syncthreads();
    }
}

extern "C" void kernel_launch(void* const* d_in, const int* in_sizes, int n_in,
                              void* d_out, int out_size) {
    const float* x  = (const float*)d_in[0];   // [T,B,I]
    const float* Wi = (const float*)d_in[1];   // [H,I]
    const float* Wh = (const float*)d_in[2];   // [H,H]
    float* out = (float*)d_out;

    const long long main_elems = (long long)kT * kB * kH;
    int write_tail = ((long long)out_size >= main_elems + (long long)kB * kH) ? 1 : 0;

    cudaFuncSetAttribute(rnn_kpair_kernel,
                         cudaFuncAttributeMaxDynamicSharedMemorySize,
                         (int)SMEM_BYTES);
    rnn_kpair_kernel<<<NG * NC, NTHR, SMEM_BYTES>>>(x, Wi, Wh, out, write_tail);
}

// round 5
// speedup vs baseline: 1.6448x; 1.1309x over previous
#include <cuda_runtime.h>
#include <stdint.h>

// ---------------------------------------------------------------------------
// Persistent fp32 RNN, k-pair packed f32x2 math, software-pipelined exchange.
//
// out[t] = tanh(x[t] @ Wi^T + h @ Wh^T),  h = out[t]
//
// 8 batch-groups x 16 H-slice CTAs = 128 CTAs, 512 threads (16 warps).
// K=768 split: h k-pairs rows [0,256), x k-pairs rows [256,384).
// Warp w owns h kp [16w,16w+16) and x kp [8w, 8w+8).
// Hd columns XOR-swizzled: phys_col = b ^ 4*((row>>3)&3)  -> conflict-free
// column STS for h-readback / x-staging, conflict-free 2xLDS.128 reads.
// x-part of step t+1 is computed between barrier-arrive and barrier-spin.
// ---------------------------------------------------------------------------

namespace {
constexpr int kT = 1024, kB = 128, kI = 256, kH = 512;
constexpr int NG = 8, BG = 16, NC = 16, JC = 32;
constexpr int NTHR = 512, NWARP = 16;
constexpr int KP_H = kH / 2;          // 256
constexpr int KP_X = kI / 2;          // 128
constexpr int KPT  = KP_H + KP_X;     // 384
constexpr int XW = KP_X / NWARP;      // 8 x k-pairs per warp
constexpr int HW = KP_H / NWARP;      // 16 h k-pairs per warp

constexpr int WS_STRIDE = 34;         // u64 per weight row
constexpr int HD_STRIDE = 18;         // u64 per Hd row (16 cols + pad)
constexpr int PS_STRIDE = 34;         // floats per Ps row

constexpr int OFF_WS = 0;
constexpr int OFF_HD = KPT * WS_STRIDE;             // u64 units
constexpr int OFF_PS = OFF_HD + KPT * HD_STRIDE;
constexpr int PS_U64 = NWARP * BG * PS_STRIDE / 2;
constexpr int SMEM_U64 = OFF_PS + PS_U64;
constexpr size_t SMEM_BYTES = size_t(SMEM_U64) * 8; // 194560 B
}

__device__ unsigned g_rnn_bar[NG];   // zero-init; monotonic across replays

__device__ __forceinline__ void fma2(unsigned long long& acc,
                                     unsigned long long a,
                                     unsigned long long b) {
    asm("fma.rn.f32x2 %0, %1, %2, %0;" : "+l"(acc) : "l"(a), "l"(b));
}

// 16 fma2 on one k-pair row: acc[jj*4+bb], w cols jq*2(+16), h cols 4 batches
#define STEP16(wp, hp)                                                       \
    do {                                                                     \
        const ulonglong2 w0 = *reinterpret_cast<const ulonglong2*>(wp);      \
        const ulonglong2 w1 = *reinterpret_cast<const ulonglong2*>((wp)+16); \
        const ulonglong2 h0 = *reinterpret_cast<const ulonglong2*>(hp);      \
        const ulonglong2 h1 = *reinterpret_cast<const ulonglong2*>((hp)+2);  \
        fma2(acc[0],  w0.x, h0.x); fma2(acc[4],  w0.y, h0.x);                \
        fma2(acc[8],  w1.x, h0.x); fma2(acc[12], w1.y, h0.x);                \
        fma2(acc[1],  w0.x, h0.y); fma2(acc[5],  w0.y, h0.y);                \
        fma2(acc[9],  w1.x, h0.y); fma2(acc[13], w1.y, h0.y);                \
        fma2(acc[2],  w0.x, h1.x); fma2(acc[6],  w0.y, h1.x);                \
        fma2(acc[10], w1.x, h1.x); fma2(acc[14], w1.y, h1.x);                \
        fma2(acc[3],  w0.x, h1.y); fma2(acc[7],  w0.y, h1.y);                \
        fma2(acc[11], w1.x, h1.y); fma2(acc[15], w1.y, h1.y);                \
    } while (0)

__global__ void __launch_bounds__(NTHR, 1)
rnn_pipe_kernel(const float* __restrict__ x,
                const float* __restrict__ Wi,
                const float* __restrict__ Wh,
                float* __restrict__ out,
                int write_tail)
{
    extern __shared__ unsigned long long smu[];
    unsigned long long* Ws = smu + OFF_WS;
    unsigned long long* Hd = smu + OFF_HD;
    float*              Ps = reinterpret_cast<float*>(smu + OFF_PS);

    const int tid = threadIdx.x;
    const int g   = blockIdx.x >> 4;
    const int c   = blockIdx.x & 15;
    const int bg0 = g * BG;
    const int jg0 = c * JC;

    // ---- prologue: weights (column-permuted), zero h, stage x[0] ----------
    {
        const int jl  = tid >> 4;                 // 0..31
        const int kpb = tid & 15;                 // 0..15
        const int dst = (jl >> 2) * 2 + ((jl >> 1) & 1) * 16 + (jl & 1);
        const float2* whp = reinterpret_cast<const float2*>(
            Wh + (size_t)(jg0 + jl) * kH);
        #pragma unroll
        for (int i = 0; i < KP_H / 16; ++i) {
            int kp = kpb + 16 * i;
            float2 v = __ldg(whp + kp);
            Ws[kp * WS_STRIDE + dst] = *reinterpret_cast<unsigned long long*>(&v);
        }
        const float2* wip = reinterpret_cast<const float2*>(
            Wi + (size_t)(jg0 + jl) * kI);
        #pragma unroll
        for (int i = 0; i < KP_X / 16; ++i) {
            int kp = kpb + 16 * i;
            float2 v = __ldg(wip + kp);
            Ws[(KP_H + kp) * WS_STRIDE + dst] =
                *reinterpret_cast<unsigned long long*>(&v);
        }
    }
    for (int e = tid; e < KP_H * HD_STRIDE; e += NTHR) Hd[e] = 0ull;
    {
        const int b = tid >> 5, l = tid & 31;
        const int col = b ^ (4 * ((l >> 3) & 3));
        const float2* xp = reinterpret_cast<const float2*>(
            x + (size_t)(bg0 + b) * kI);
        #pragma unroll
        for (int i = 0; i < 4; ++i) {
            float2 v = __ldcg(xp + l + 32 * i);
            Hd[(KP_H + l + 32 * i) * HD_STRIDE + col] =
                *reinterpret_cast<unsigned long long*>(&v);
        }
    }
    __syncthreads();

    // ---- per-thread geometry ----------------------------------------------
    const int w    = tid >> 5;
    const int lane = tid & 31;
    const int jq   = lane & 7;           // j quad index
    const int bp   = lane >> 3;          // batch quad index
    const int rb   = w, rl = lane;       // reduce/readback roles
    const int wrcol = rb ^ (4 * ((rl >> 3) & 3));   // swizzled write column

    const unsigned long long* wx  = Ws + (size_t)(KP_H + XW * w) * WS_STRIDE + jq * 2;
    const unsigned long long* hx  = Hd + (size_t)(KP_H + XW * w) * HD_STRIDE
                                       + 4 * (bp ^ (w & 3));
    const unsigned long long* wh0 = Ws + (size_t)(HW * w) * WS_STRIDE + jq * 2;
    const unsigned long long* hh0 = Hd + (size_t)(HW * w) * HD_STRIDE
                                       + 4 * (bp ^ ((2 * w) & 3));
    const unsigned long long* wh1 = Ws + (size_t)(HW * w + 8) * WS_STRIDE + jq * 2;
    const unsigned long long* hh1 = Hd + (size_t)(HW * w + 8) * HD_STRIDE
                                       + 4 * (bp ^ ((2 * w + 1) & 3));

    unsigned long long acc[16];

    // ---- x-part for t=0 -----------------------------------------------------
    {
        #pragma unroll
        for (int i = 0; i < 16; ++i) acc[i] = 0ull;
        const unsigned long long* wp = wx;
        const unsigned long long* hp = hx;
        #pragma unroll
        for (int i = 0; i < XW; ++i) { STEP16(wp, hp); wp += WS_STRIDE; hp += HD_STRIDE; }
    }

    for (int t = 0; t < kT; ++t) {
        // ---- h-part: 2 blocks of 8 k-pairs ---------------------------------
        {
            const unsigned long long* wp = wh0;
            const unsigned long long* hp = hh0;
            #pragma unroll
            for (int i = 0; i < 8; ++i) { STEP16(wp, hp); wp += WS_STRIDE; hp += HD_STRIDE; }
            wp = wh1; hp = hh1;
            #pragma unroll
            for (int i = 0; i < 8; ++i) { STEP16(wp, hp); wp += WS_STRIDE; hp += HD_STRIDE; }
        }

        // ---- scatter partials (conflict-free scalar stores) ----------------
        // j = 4*jq + jj  ->  column cf = jj*8 + jq
        #pragma unroll
        for (int bb = 0; bb < 4; ++bb) {
            const int row = (w * BG + 4 * bp + bb) * PS_STRIDE;
            #pragma unroll
            for (int jj = 0; jj < 4; ++jj) {
                float2 f = *reinterpret_cast<float2*>(&acc[jj * 4 + bb]);
                Ps[row + jj * 8 + jq] = f.x + f.y;
            }
        }

        // ---- prefetch x[t+1] ------------------------------------------------
        float2 xr[4];
        if (t + 1 < kT) {
            const float2* xp = reinterpret_cast<const float2*>(
                x + (size_t)(t + 1) * kB * kI + (size_t)(bg0 + rb) * kI);
            #pragma unroll
            for (int i = 0; i < 4; ++i) xr[i] = __ldcg(xp + rl + 32 * i);
        }
        __syncthreads();                                   // (1) Ps ready

        // ---- tree-reduce 16 partials, tanh, store out[t] --------------------
        {
            const int cf = (rl & 3) * 8 + (rl >> 2);       // matches scatter
            float p[16];
            #pragma unroll
            for (int ws = 0; ws < NWARP; ++ws)
                p[ws] = Ps[(ws * BG + rb) * PS_STRIDE + cf];
            #pragma unroll
            for (int s = 8; s >= 1; s >>= 1)
                #pragma unroll
                for (int i = 0; i < s; ++i) p[i] += p[i + s];
            float r = tanhf(p[0]);
            size_t o = (size_t)t * kB * kH + (size_t)(bg0 + rb) * kH + jg0 + rl;
            out[o] = r;
            if (t == kT - 1 && write_tail)
                out[(size_t)kT * kB * kH + (size_t)(bg0 + rb) * kH + jg0 + rl] = r;
        }
        if (t + 1 == kT) break;

        // ---- stage x[t+1] into Hd (swizzled, conflict-free) -----------------
        #pragma unroll
        for (int i = 0; i < 4; ++i)
            Hd[(KP_H + rl + 32 * i) * HD_STRIDE + wrcol] =
                *reinterpret_cast<unsigned long long*>(&xr[i]);

        __threadfence();
        __syncthreads();                                   // (2) out visible, x staged

        unsigned target = 0;
        if (tid == 0) {
            unsigned old = atomicAdd(&g_rnn_bar[g], 1u);   // arrive
            target = ((old >> 4) + 1u) << 4;
        }

        // ---- x-part(t+1): overlaps barrier latency --------------------------
        {
            #pragma unroll
            for (int i = 0; i < 16; ++i) acc[i] = 0ull;
            const unsigned long long* wp = wx;
            const unsigned long long* hp = hx;
            #pragma unroll
            for (int i = 0; i < XW; ++i) { STEP16(wp, hp); wp += WS_STRIDE; hp += HD_STRIDE; }
        }

        if (tid == 0) {                                    // spin (mostly done)
            unsigned cur;
            do {
                asm volatile("ld.acquire.gpu.global.u32 %0, [%1];"
                             : "=r"(cur) : "l"(&g_rnn_bar[g]) : "memory");
            } while (cur < target);
        }
        __syncthreads();                                   // (3) h[t] available

        // ---- read back full h into Hd (swizzled, conflict-free) -------------
        {
            const float2* op = reinterpret_cast<const float2*>(
                out + (size_t)t * kB * kH + (size_t)(bg0 + rb) * kH);
            float2 hv[8];
            #pragma unroll
            for (int i = 0; i < 8; ++i) hv[i] = __ldcg(op + rl + 32 * i);
            #pragma unroll
            for (int i = 0; i < 8; ++i)
                Hd[(rl + 32 * i) * HD_STRIDE + wrcol] =
                    *reinterpret_cast<unsigned long long*>(&hv[i]);
        }
        __syncthreads();                                   // (4)
    }
}

extern "C" void kernel_launch(void* const* d_in, const int* in_sizes, int n_in,
                              void* d_out, int out_size) {
    const float* x  = (const float*)d_in[0];   // [T,B,I]
    const float* Wi = (const float*)d_in[1];   // [H,I]
    const float* Wh = (const float*)d_in[2];   // [H,H]
    float* out = (float*)d_out;

    const long long main_elems = (long long)kT * kB * kH;
    int write_tail = ((long long)out_size >= main_elems + (long long)kB * kH) ? 1 : 0;

    cudaFuncSetAttribute(rnn_pipe_kernel,
                         cudaFuncAttributeMaxDynamicSharedMemorySize,
                         (int)SMEM_BYTES);
    rnn_pipe_kernel<<<NG * NC, NTHR, SMEM_BYTES>>>(x, Wi, Wh, out, write_tail);
}

// round 6
// speedup vs baseline: 1.9720x; 1.1989x over previous
#include <cuda_runtime.h>
#include <stdint.h>

// ---------------------------------------------------------------------------
// Persistent fp32 RNN, k-pair packed f32x2 math, fine-grained producer flags.
//
// out[t] = tanh(x[t] @ Wi^T + h @ Wh^T),  h = out[t]
//
// 8 batch-groups x 16 H-slice CTAs = 128 CTAs, 512 threads (16 warps).
// Warp w of CTA (g,c) consumes exactly producer CTA (g,w)'s h slice
// (j in [32w,32w+32)), staged into warp-PRIVATE Hd rows [16w,16w+16).
// Inter-CTA sync = per-CTA monotonic release-flag; no group barrier.
// x-part of step t+1 overlaps the signal->wait window.
// ---------------------------------------------------------------------------

namespace {
constexpr int kT = 1024, kB = 128, kI = 256, kH = 512;
constexpr int NG = 8, BG = 16, NC = 16, JC = 32;
constexpr int NTHR = 512, NWARP = 16;
constexpr int KP_H = kH / 2;          // 256
constexpr int KP_X = kI / 2;          // 128
constexpr int KPT  = KP_H + KP_X;     // 384
constexpr int XW = KP_X / NWARP;      // 8 x k-pairs per warp
constexpr int HW = KP_H / NWARP;      // 16 h k-pairs per warp

constexpr int WS_STRIDE = 34;         // u64 per weight row
constexpr int HD_STRIDE = 18;         // u64 per Hd row (16 cols + pad)
constexpr int PS_STRIDE = 34;         // floats per Ps row

constexpr int OFF_WS = 0;
constexpr int OFF_HD = KPT * WS_STRIDE;             // u64 units
constexpr int OFF_PS = OFF_HD + KPT * HD_STRIDE;
constexpr int PS_U64 = NWARP * BG * PS_STRIDE / 2;
constexpr int OFF_AUX = OFF_PS + PS_U64;            // 1 u64: flag base
constexpr int SMEM_U64 = OFF_AUX + 1;
constexpr size_t SMEM_BYTES = size_t(SMEM_U64) * 8;
}

__device__ unsigned g_rnn_flag[NG * NC];   // zero-init; monotonic forever

__device__ __forceinline__ void fma2(unsigned long long& acc,
                                     unsigned long long a,
                                     unsigned long long b) {
    asm("fma.rn.f32x2 %0, %1, %2, %0;" : "+l"(acc) : "l"(a), "l"(b));
}

#define STEP16(wp, hp)                                                       \
    do {                                                                     \
        const ulonglong2 w0 = *reinterpret_cast<const ulonglong2*>(wp);      \
        const ulonglong2 w1 = *reinterpret_cast<const ulonglong2*>((wp)+16); \
        const ulonglong2 h0 = *reinterpret_cast<const ulonglong2*>(hp);      \
        const ulonglong2 h1 = *reinterpret_cast<const ulonglong2*>((hp)+2);  \
        fma2(acc[0],  w0.x, h0.x); fma2(acc[4],  w0.y, h0.x);                \
        fma2(acc[8],  w1.x, h0.x); fma2(acc[12], w1.y, h0.x);                \
        fma2(acc[1],  w0.x, h0.y); fma2(acc[5],  w0.y, h0.y);                \
        fma2(acc[9],  w1.x, h0.y); fma2(acc[13], w1.y, h0.y);                \
        fma2(acc[2],  w0.x, h1.x); fma2(acc[6],  w0.y, h1.x);                \
        fma2(acc[10], w1.x, h1.x); fma2(acc[14], w1.y, h1.x);                \
        fma2(acc[3],  w0.x, h1.y); fma2(acc[7],  w0.y, h1.y);                \
        fma2(acc[11], w1.x, h1.y); fma2(acc[15], w1.y, h1.y);                \
    } while (0)

__global__ void __launch_bounds__(NTHR, 1)
rnn_flag_kernel(const float* __restrict__ x,
                const float* __restrict__ Wi,
                const float* __restrict__ Wh,
                float* __restrict__ out,
                int write_tail)
{
    extern __shared__ unsigned long long smu[];
    unsigned long long* Ws = smu + OFF_WS;
    unsigned long long* Hd = smu + OFF_HD;
    float*              Ps = reinterpret_cast<float*>(smu + OFF_PS);
    unsigned*           Aux = reinterpret_cast<unsigned*>(smu + OFF_AUX);

    const int tid = threadIdx.x;
    const int g   = blockIdx.x >> 4;
    const int c   = blockIdx.x & 15;
    const int bg0 = g * BG;
    const int jg0 = c * JC;

    // ---- prologue ----------------------------------------------------------
    if (tid == 0) Aux[0] = g_rnn_flag[blockIdx.x];   // own flag == all flags

    {   // weights, column-permuted (same as R5)
        const int jl  = tid >> 4;
        const int kpb = tid & 15;
        const int dst = (jl >> 2) * 2 + ((jl >> 1) & 1) * 16 + (jl & 1);
        const float2* whp = reinterpret_cast<const float2*>(
            Wh + (size_t)(jg0 + jl) * kH);
        #pragma unroll
        for (int i = 0; i < KP_H / 16; ++i) {
            int kp = kpb + 16 * i;
            float2 v = __ldg(whp + kp);
            Ws[kp * WS_STRIDE + dst] = *reinterpret_cast<unsigned long long*>(&v);
        }
        const float2* wip = reinterpret_cast<const float2*>(
            Wi + (size_t)(jg0 + jl) * kI);
        #pragma unroll
        for (int i = 0; i < KP_X / 16; ++i) {
            int kp = kpb + 16 * i;
            float2 v = __ldg(wip + kp);
            Ws[(KP_H + kp) * WS_STRIDE + dst] =
                *reinterpret_cast<unsigned long long*>(&v);
        }
    }
    for (int e = tid; e < KP_H * HD_STRIDE; e += NTHR) Hd[e] = 0ull;
    {   // x[0]
        const int b = tid >> 5, l = tid & 31;
        const int col = b ^ (4 * ((l >> 3) & 3));
        const float2* xp = reinterpret_cast<const float2*>(
            x + (size_t)(bg0 + b) * kI);
        #pragma unroll
        for (int i = 0; i < 4; ++i) {
            float2 v = __ldcg(xp + l + 32 * i);
            Hd[(KP_H + l + 32 * i) * HD_STRIDE + col] =
                *reinterpret_cast<unsigned long long*>(&v);
        }
    }
    __syncthreads();
    const unsigned base = Aux[0];

    // ---- per-thread geometry ------------------------------------------------
    const int w    = tid >> 5;
    const int lane = tid & 31;
    const int jq   = lane & 7;
    const int bp   = lane >> 3;
    const int rb   = w, rl = lane;
    const int wrcol = rb ^ (4 * ((rl >> 3) & 3));

    // producer flag for this warp's h slice
    volatile unsigned* flagp = g_rnn_flag + (g * NC + w);
    unsigned* myflag = g_rnn_flag + blockIdx.x;

    // readback geometry (warp w <- producer CTA (g,w), j in [32w,32w+32))
    const int p    = lane & 15;              // j-pair row within chunk
    const int bh   = (lane >> 4) * 8;        // batch half
    const int pge8 = (p >> 3) & 1;           // parity selector
    const int hswz = 4 * ((2 * w + pge8) & 3);

    const unsigned long long* wx  = Ws + (size_t)(KP_H + XW * w) * WS_STRIDE + jq * 2;
    const unsigned long long* hx  = Hd + (size_t)(KP_H + XW * w) * HD_STRIDE
                                       + 4 * (bp ^ (w & 3));
    const unsigned long long* wh0 = Ws + (size_t)(HW * w) * WS_STRIDE + jq * 2;
    const unsigned long long* hh0 = Hd + (size_t)(HW * w) * HD_STRIDE
                                       + 4 * (bp ^ ((2 * w) & 3));
    const unsigned long long* wh1 = Ws + (size_t)(HW * w + 8) * WS_STRIDE + jq * 2;
    const unsigned long long* hh1 = Hd + (size_t)(HW * w + 8) * HD_STRIDE
                                       + 4 * (bp ^ ((2 * w + 1) & 3));

    unsigned long long acc[16];

    // ---- x-part for t=0 ------------------------------------------------------
    {
        #pragma unroll
        for (int i = 0; i < 16; ++i) acc[i] = 0ull;
        const unsigned long long* wp = wx;
        const unsigned long long* hp = hx;
        #pragma unroll
        for (int i = 0; i < XW; ++i) { STEP16(wp, hp); wp += WS_STRIDE; hp += HD_STRIDE; }
    }

    for (int t = 0; t < kT; ++t) {
        // ---- h-part ----------------------------------------------------------
        {
            const unsigned long long* wp = wh0;
            const unsigned long long* hp = hh0;
            #pragma unroll
            for (int i = 0; i < 8; ++i) { STEP16(wp, hp); wp += WS_STRIDE; hp += HD_STRIDE; }
            wp = wh1; hp = hh1;
            #pragma unroll
            for (int i = 0; i < 8; ++i) { STEP16(wp, hp); wp += WS_STRIDE; hp += HD_STRIDE; }
        }

        // ---- scatter partials (conflict-free) --------------------------------
        #pragma unroll
        for (int bb = 0; bb < 4; ++bb) {
            const int row = (w * BG + 4 * bp + bb) * PS_STRIDE;
            #pragma unroll
            for (int jj = 0; jj < 4; ++jj) {
                float2 f = *reinterpret_cast<float2*>(&acc[jj * 4 + bb]);
                Ps[row + jj * 8 + jq] = f.x + f.y;
            }
        }

        // ---- prefetch x[t+1] ---------------------------------------------------
        float2 xr[4];
        if (t + 1 < kT) {
            const float2* xp = reinterpret_cast<const float2*>(
                x + (size_t)(t + 1) * kB * kI + (size_t)(bg0 + rb) * kI);
            #pragma unroll
            for (int i = 0; i < 4; ++i) xr[i] = __ldcg(xp + rl + 32 * i);
        }
        __syncthreads();                                   // S1: Ps ready

        // ---- reduce, tanh, store out[t] ---------------------------------------
        {
            const int cf = (rl & 3) * 8 + (rl >> 2);
            float pv[16];
            #pragma unroll
            for (int ws = 0; ws < NWARP; ++ws)
                pv[ws] = Ps[(ws * BG + rb) * PS_STRIDE + cf];
            #pragma unroll
            for (int s = 8; s >= 1; s >>= 1)
                #pragma unroll
                for (int i = 0; i < s; ++i) pv[i] += pv[i + s];
            float r = tanhf(pv[0]);
            size_t o = (size_t)t * kB * kH + (size_t)(bg0 + rb) * kH + jg0 + rl;
            out[o] = r;
            if (t == kT - 1 && write_tail)
                out[(size_t)kT * kB * kH + (size_t)(bg0 + rb) * kH + jg0 + rl] = r;
        }
        if (t + 1 == kT) break;

        // ---- stage x[t+1] ------------------------------------------------------
        #pragma unroll
        for (int i = 0; i < 4; ++i)
            Hd[(KP_H + rl + 32 * i) * HD_STRIDE + wrcol] =
                *reinterpret_cast<unsigned long long*>(&xr[i]);

        __syncthreads();                                   // S2: STG + x staged

        if (tid == 0) {                                    // release out[t]
            asm volatile("red.release.gpu.global.add.u32 [%0], %1;"
                         :: "l"(myflag), "r"(1u) : "memory");
        }

        // ---- x-part(t+1): overlaps producer wait -------------------------------
        {
            #pragma unroll
            for (int i = 0; i < 16; ++i) acc[i] = 0ull;
            const unsigned long long* wp = wx;
            const unsigned long long* hp = hx;
            #pragma unroll
            for (int i = 0; i < XW; ++i) { STEP16(wp, hp); wp += WS_STRIDE; hp += HD_STRIDE; }
        }

        // ---- wait single producer, read its h slice, stage (warp-private) -----
        {
            const unsigned target = base + (unsigned)(t + 1);
            unsigned cur;
            do {
                asm volatile("ld.acquire.gpu.global.u32 %0, [%1];"
                             : "=r"(cur) : "l"((const unsigned*)flagp) : "memory");
            } while ((int)(cur - target) < 0);

            const float* hb = out + (size_t)t * kB * kH + (size_t)bg0 * kH
                                  + 32 * w + 2 * p;
            float2 hv[8];
            #pragma unroll
            for (int i = 0; i < 8; ++i) {
                const int brd = ((((2 * i) & 6) | (i >> 2)) ^ pge8);
                hv[i] = __ldcg(reinterpret_cast<const float2*>(
                    hb + (size_t)(bh + brd) * kH));
            }
            #pragma unroll
            for (int i = 0; i < 8; ++i) {
                const int brd = ((((2 * i) & 6) | (i >> 2)) ^ pge8);
                Hd[(16 * w + p) * HD_STRIDE + ((bh + brd) ^ hswz)] =
                    *reinterpret_cast<unsigned long long*>(&hv[i]);
            }
            __syncwarp();
        }
    }
}

extern "C" void kernel_launch(void* const* d_in, const int* in_sizes, int n_in,
                              void* d_out, int out_size) {
    const float* x  = (const float*)d_in[0];   // [T,B,I]
    const float* Wi = (const float*)d_in[1];   // [H,I]
    const float* Wh = (const float*)d_in[2];   // [H,H]
    float* out = (float*)d_out;

    const long long main_elems = (long long)kT * kB * kH;
    int write_tail = ((long long)out_size >= main_elems + (long long)kB * kH) ? 1 : 0;

    cudaFuncSetAttribute(rnn_flag_kernel,
                         cudaFuncAttributeMaxDynamicSharedMemorySize,
                         (int)SMEM_BYTES);
    rnn_flag_kernel<<<NG * NC, NTHR, SMEM_BYTES>>>(x, Wi, Wh, out, write_tail);
}